// round 7
// baseline (speedup 1.0000x reference)
#include <cuda_runtime.h>
#include <cuda_fp16.h>
#include <stdint.h>
#include <math.h>

// ---------------------------------------------------------------------------
// SwinV2 WindowAttention via HMMA (mma.sync.m16n8k16 fp16->fp32).
// 4096 windows, N=64 tok, C=192, H=6, HD=32. 1 window/CTA, 256 threads.
// ---------------------------------------------------------------------------

#define NWIN 4096
#define STR  200          // row stride (halves) for X/Q/K/O/W tiles: 400B, conflict-free
#define VSTR 72           // row stride (halves) for vt/P: 144B, conflict-free

// smem byte offsets
#define OFF_XS 0          // X fp16 [64][STR], later O
#define OFF_WT 25600      // weight tile fp16 [192][STR]
#define OFF_QH 102400     // Qhat fp16 [64][STR]
#define OFF_KH 128000     // Khat fp16 [64][STR]
#define OFF_VT 153600     // Vt fp16 [192][VSTR]
#define OFF_SS 181248     // scores f32 [64][72]
#define OFF_P  199680     // P fp16 [64][VSTR]
#define OFF_SC 208896     // 6 floats
#define SMEM_BYTES 208960

__device__ __align__(16) __half g_wt[4 * 192 * STR];   // fp16 Wt[n][k] images (q,k,v,proj)
__device__ float g_bias[6 * 64 * 64];

// ---------------- helpers ----------------
__device__ __forceinline__ uint32_t smem_u32(const void* p) {
    uint32_t a;
    asm("{ .reg .u64 t; cvta.to.shared.u64 t, %1; cvt.u32.u64 %0, t; }" : "=r"(a) : "l"(p));
    return a;
}
__device__ __forceinline__ void ldsm4(uint32_t addr, uint32_t r[4]) {
    asm volatile("ldmatrix.sync.aligned.m8n8.x4.shared.b16 {%0,%1,%2,%3}, [%4];"
        : "=r"(r[0]), "=r"(r[1]), "=r"(r[2]), "=r"(r[3]) : "r"(addr));
}
__device__ __forceinline__ void ldsm2(uint32_t addr, uint32_t r[2]) {
    asm volatile("ldmatrix.sync.aligned.m8n8.x2.shared.b16 {%0,%1}, [%2];"
        : "=r"(r[0]), "=r"(r[1]) : "r"(addr));
}
__device__ __forceinline__ void mma16816(float c[4], const uint32_t a[4], uint32_t b0, uint32_t b1) {
    asm volatile("mma.sync.aligned.m16n8k16.row.col.f32.f16.f16.f32 "
        "{%0,%1,%2,%3}, {%4,%5,%6,%7}, {%8,%9}, {%0,%1,%2,%3};"
        : "+f"(c[0]), "+f"(c[1]), "+f"(c[2]), "+f"(c[3])
        : "r"(a[0]), "r"(a[1]), "r"(a[2]), "r"(a[3]), "r"(b0), "r"(b1));
}
__device__ __forceinline__ uint32_t pack2(float a, float b) {
    __half2 h = __floats2half2_rn(a, b);
    return *reinterpret_cast<uint32_t*>(&h);
}

// ---------------- prologue kernels ----------------
__global__ void prep_w_kernel(const float* __restrict__ qw, const float* __restrict__ kw,
                              const float* __restrict__ vw, const float* __restrict__ pw)
{
    int i = blockIdx.x * 256 + threadIdx.x;           // 576*256 = 147456 = 4*192*192
    int w = i / 36864, r = i % 36864;
    int k = r / 192, n = r % 192;
    const float* W = (w == 0) ? qw : (w == 1) ? kw : (w == 2) ? vw : pw;
    g_wt[w * 192 * STR + n * STR + k] = __float2half(W[k * 192 + n]);
}

__global__ void bias_kernel(const float* __restrict__ fc1_w, const float* __restrict__ fc1_b,
                            const float* __restrict__ fc2_w)
{
    __shared__ float tb[225 * 6];
    int tid = threadIdx.x;
    if (tid < 225) {
        int i = tid / 15, j = tid % 15;
        float v0 = (float)(j - 7) * (8.0f / 7.0f);
        float v1 = (float)(i - 7) * (8.0f / 7.0f);
        float s0 = (v0 > 0.f) ? 1.f : ((v0 < 0.f) ? -1.f : 0.f);
        float s1 = (v1 > 0.f) ? 1.f : ((v1 < 0.f) ? -1.f : 0.f);
        v0 = s0 * log2f(fabsf(v0) + 1.0f) * (1.0f / 3.0f);
        v1 = s1 * log2f(fabsf(v1) + 1.0f) * (1.0f / 3.0f);
        float acc[6];
#pragma unroll
        for (int h = 0; h < 6; h++) acc[h] = 0.f;
        for (int u = 0; u < 512; u++) {
            float hv = fmaxf(v0 * fc1_w[u] + v1 * fc1_w[512 + u] + fc1_b[u], 0.f);
#pragma unroll
            for (int h = 0; h < 6; h++) acc[h] += hv * fc2_w[u * 6 + h];
        }
#pragma unroll
        for (int h = 0; h < 6; h++) tb[tid * 6 + h] = acc[h];
    }
    __syncthreads();
    for (int i = tid; i < 6 * 64 * 64; i += blockDim.x) {
        int h = i >> 12, pq = i & 4095, p = pq >> 6, q = pq & 63;
        int idx = ((p >> 3) - (q >> 3) + 7) * 15 + ((p & 7) - (q & 7) + 7);
        g_bias[i] = 16.0f / (1.0f + __expf(-tb[idx * 6 + h]));
    }
}

// ---------------- main kernel ----------------
__device__ __forceinline__ void stage_w(char* smc, int widx, int tid) {
    const float4* s = (const float4*)(g_wt + widx * 192 * STR);
    float4* d = (float4*)(smc + OFF_WT);
    for (int i = tid; i < 192 * STR * 2 / 16; i += 256) d[i] = s[i];
}

// M=64, N=192, K=192: warp w -> N cols [w*24, w*24+24)
__device__ __forceinline__ void gemm192(uint32_t a_su, uint32_t w_su, int warp, int lane,
                                        float c[12][4])
{
#pragma unroll
    for (int i = 0; i < 12; i++) { c[i][0] = c[i][1] = c[i][2] = c[i][3] = 0.f; }
    const int wn = warp * 24;
    const uint32_t arow = (lane & 15), ak8 = (lane >> 4) * 8;
    const uint32_t brow = (lane & 7),  bk8 = ((lane >> 3) & 1) * 8;
#pragma unroll
    for (int ks = 0; ks < 12; ks++) {
        uint32_t A[4][4];
#pragma unroll
        for (int mt = 0; mt < 4; mt++)
            ldsm4(a_su + ((mt * 16 + arow) * STR + ks * 16 + ak8) * 2, A[mt]);
#pragma unroll
        for (int nt = 0; nt < 3; nt++) {
            uint32_t B[2];
            ldsm2(w_su + ((wn + nt * 8 + brow) * STR + ks * 16 + bk8) * 2, B);
#pragma unroll
            for (int mt = 0; mt < 4; mt++) mma16816(c[mt * 3 + nt], A[mt], B[0], B[1]);
        }
    }
}

// L2-normalize rows of a [64][192] fp16 tile per (token, head) slice of 32
__device__ __forceinline__ void norm_rows(char* smc, uint32_t off, const float* scs,
                                          bool useScale, int tid)
{
    for (int p = tid; p < 384; p += 256) {
        int h = p >> 6, m = p & 63;
        __half2* ptr = (__half2*)(smc + off + (m * STR + h * 32) * 2);
        float s = 0.f;
        __half2 vv[16];
#pragma unroll
        for (int j = 0; j < 16; j++) {
            vv[j] = ptr[j];
            float2 f = __half22float2(vv[j]);
            s += f.x * f.x + f.y * f.y;
        }
        float scl = rsqrtf(s) * (useScale ? scs[h] : 1.f);
        __half2 hs = __floats2half2_rn(scl, scl);
#pragma unroll
        for (int j = 0; j < 16; j++) ptr[j] = __hmul2(vv[j], hs);
    }
}

__global__ void __launch_bounds__(256, 1)
win_attn_hmma(const float* __restrict__ x_g, const float* __restrict__ mask_g,
              const float* __restrict__ lsc,
              const float* __restrict__ qb, const float* __restrict__ vb,
              const float* __restrict__ pb, float* __restrict__ out_g)
{
    extern __shared__ char smc[];
    const uint32_t su = smem_u32(smc);
    const int tid = threadIdx.x, warp = tid >> 5, lane = tid & 31;
    const int blk = blockIdx.x;
    const int r = lane >> 2, cc = (lane & 3) * 2;
    float* scs = (float*)(smc + OFF_SC);
    float c[12][4];

    // ---- load X -> fp16 smem; stage Wq ----
    {
        const float4* xg = (const float4*)(x_g + (size_t)blk * 64 * 192);
#pragma unroll
        for (int i = 0; i < 12; i++) {
            int e = tid + i * 256;               // 3072 float4
            int row = e / 48, c4 = e % 48;
            float4 v = xg[e];
            char* p = smc + OFF_XS + (row * STR + c4 * 4) * 2;
            *(uint32_t*)(p)     = pack2(v.x, v.y);
            *(uint32_t*)(p + 4) = pack2(v.z, v.w);
        }
    }
    stage_w(smc, 0, tid);
    if (tid < 6) scs[tid] = __expf(fminf(lsc[tid], 4.60517019f));
    __syncthreads();

    // ---- Q ----
    gemm192(su + OFF_XS, su + OFF_WT, warp, lane, c);
#pragma unroll
    for (int mt = 0; mt < 4; mt++)
#pragma unroll
        for (int nt = 0; nt < 3; nt++) {
            int n = warp * 24 + nt * 8 + cc, m = mt * 16 + r;
            float b0 = qb[n], b1 = qb[n + 1];
            *(uint32_t*)(smc + OFF_QH + (m * STR + n) * 2)       = pack2(c[mt*3+nt][0] + b0, c[mt*3+nt][1] + b1);
            *(uint32_t*)(smc + OFF_QH + ((m + 8) * STR + n) * 2) = pack2(c[mt*3+nt][2] + b0, c[mt*3+nt][3] + b1);
        }
    __syncthreads();
    norm_rows(smc, OFF_QH, scs, true, tid);
    stage_w(smc, 1, tid);
    __syncthreads();

    // ---- K ----
    gemm192(su + OFF_XS, su + OFF_WT, warp, lane, c);
#pragma unroll
    for (int mt = 0; mt < 4; mt++)
#pragma unroll
        for (int nt = 0; nt < 3; nt++) {
            int n = warp * 24 + nt * 8 + cc, m = mt * 16 + r;
            *(uint32_t*)(smc + OFF_KH + (m * STR + n) * 2)       = pack2(c[mt*3+nt][0], c[mt*3+nt][1]);
            *(uint32_t*)(smc + OFF_KH + ((m + 8) * STR + n) * 2) = pack2(c[mt*3+nt][2], c[mt*3+nt][3]);
        }
    __syncthreads();
    norm_rows(smc, OFF_KH, scs, false, tid);
    stage_w(smc, 2, tid);
    __syncthreads();

    // ---- V (written transposed: vt[dim][token]) ----
    gemm192(su + OFF_XS, su + OFF_WT, warp, lane, c);
#pragma unroll
    for (int mt = 0; mt < 4; mt++)
#pragma unroll
        for (int nt = 0; nt < 3; nt++) {
            int n = warp * 24 + nt * 8 + cc, m = mt * 16 + r;
            float b0 = vb[n], b1 = vb[n + 1];
            *(__half*)(smc + OFF_VT + (n * VSTR + m) * 2)           = __float2half(c[mt*3+nt][0] + b0);
            *(__half*)(smc + OFF_VT + ((n + 1) * VSTR + m) * 2)     = __float2half(c[mt*3+nt][1] + b1);
            *(__half*)(smc + OFF_VT + (n * VSTR + m + 8) * 2)       = __float2half(c[mt*3+nt][2] + b0);
            *(__half*)(smc + OFF_VT + ((n + 1) * VSTR + m + 8) * 2) = __float2half(c[mt*3+nt][3] + b1);
        }
    __syncthreads();

    // ---- attention, per head ----
    const uint32_t arow = (lane & 15), ak8 = (lane >> 4) * 8;
    const uint32_t brow = (lane & 7),  bk8 = ((lane >> 3) & 1) * 8;
    const int srow = tid >> 2, q4 = tid & 3;
    const float* bi_base = g_bias + srow * 64 + q4 * 16;
    const float* mk = mask_g + (size_t)(blk & 1023) * 4096 + srow * 64 + q4 * 16;

    for (int h = 0; h < 6; h++) {
        // S = Qhat @ Khat^T : M=64, N=64 (warp: 8 cols), K=32
        float cs[4][4];
#pragma unroll
        for (int i = 0; i < 4; i++) { cs[i][0] = cs[i][1] = cs[i][2] = cs[i][3] = 0.f; }
#pragma unroll
        for (int ks = 0; ks < 2; ks++) {
            uint32_t A[4][4], B[2];
#pragma unroll
            for (int mt = 0; mt < 4; mt++)
                ldsm4(su + OFF_QH + ((mt * 16 + arow) * STR + h * 32 + ks * 16 + ak8) * 2, A[mt]);
            ldsm2(su + OFF_KH + ((warp * 8 + brow) * STR + h * 32 + ks * 16 + bk8) * 2, B);
#pragma unroll
            for (int mt = 0; mt < 4; mt++) mma16816(cs[mt], A[mt], B[0], B[1]);
        }
#pragma unroll
        for (int mt = 0; mt < 4; mt++) {
            int m = mt * 16 + r, n = warp * 8 + cc;
            *(float2*)(smc + OFF_SS + (m * 72 + n) * 4)       = make_float2(cs[mt][0], cs[mt][1]);
            *(float2*)(smc + OFF_SS + ((m + 8) * 72 + n) * 4) = make_float2(cs[mt][2], cs[mt][3]);
        }
        __syncthreads();

        // softmax: quad per row, 16 cols per thread
        {
            const float* ssr = (const float*)(smc + OFF_SS) + srow * 72 + q4 * 16;
            const float* bi = bi_base + h * 4096;
            float l[16];
#pragma unroll
            for (int j = 0; j < 16; j += 4) {
                float4 s4 = *(const float4*)(ssr + j);
                float4 b4 = *(const float4*)(bi + j);
                float4 m4 = *(const float4*)(mk + j);
                l[j + 0] = s4.x + b4.x + m4.x;
                l[j + 1] = s4.y + b4.y + m4.y;
                l[j + 2] = s4.z + b4.z + m4.z;
                l[j + 3] = s4.w + b4.w + m4.w;
            }
            float mx = l[0];
#pragma unroll
            for (int j = 1; j < 16; j++) mx = fmaxf(mx, l[j]);
            mx = fmaxf(mx, __shfl_xor_sync(0xffffffffu, mx, 1));
            mx = fmaxf(mx, __shfl_xor_sync(0xffffffffu, mx, 2));
            float sum = 0.f;
#pragma unroll
            for (int j = 0; j < 16; j++) { l[j] = __expf(l[j] - mx); sum += l[j]; }
            sum += __shfl_xor_sync(0xffffffffu, sum, 1);
            sum += __shfl_xor_sync(0xffffffffu, sum, 2);
            float inv = 1.0f / sum;
            uint32_t* pr = (uint32_t*)(smc + OFF_P + (srow * VSTR + q4 * 16) * 2);
#pragma unroll
            for (int j = 0; j < 8; j++) pr[j] = pack2(l[2 * j] * inv, l[2 * j + 1] * inv);
        }
        __syncthreads();

        // O_h = P @ Vt_h : M=64, N=32, K=64. warp grid 2(M) x 4(N)
        {
            int mw = warp >> 2, nw = warp & 3;
            float co[2][4];
            co[0][0]=co[0][1]=co[0][2]=co[0][3]=0.f;
            co[1][0]=co[1][1]=co[1][2]=co[1][3]=0.f;
#pragma unroll
            for (int ks = 0; ks < 4; ks++) {
                uint32_t A[2][4], B[2];
#pragma unroll
                for (int mt = 0; mt < 2; mt++)
                    ldsm4(su + OFF_P + (((mw * 2 + mt) * 16 + arow) * VSTR + ks * 16 + ak8) * 2, A[mt]);
                ldsm2(su + OFF_VT + ((h * 32 + nw * 8 + brow) * VSTR + ks * 16 + bk8) * 2, B);
#pragma unroll
                for (int mt = 0; mt < 2; mt++) mma16816(co[mt], A[mt], B[0], B[1]);
            }
#pragma unroll
            for (int mt = 0; mt < 2; mt++) {
                int m = mw * 32 + mt * 16 + r, n = h * 32 + nw * 8 + cc;
                *(uint32_t*)(smc + OFF_XS + (m * STR + n) * 2)       = pack2(co[mt][0], co[mt][1]);
                *(uint32_t*)(smc + OFF_XS + ((m + 8) * STR + n) * 2) = pack2(co[mt][2], co[mt][3]);
            }
        }
        __syncthreads();
    }

    // ---- proj ----
    stage_w(smc, 3, tid);
    __syncthreads();
    gemm192(su + OFF_XS, su + OFF_WT, warp, lane, c);
    {
        float* og = out_g + (size_t)blk * 64 * 192;
#pragma unroll
        for (int mt = 0; mt < 4; mt++)
#pragma unroll
            for (int nt = 0; nt < 3; nt++) {
                int n = warp * 24 + nt * 8 + cc, m = mt * 16 + r;
                float b0 = pb[n], b1 = pb[n + 1];
                *(float2*)(og + m * 192 + n)       = make_float2(c[mt*3+nt][0] + b0, c[mt*3+nt][1] + b1);
                *(float2*)(og + (m + 8) * 192 + n) = make_float2(c[mt*3+nt][2] + b0, c[mt*3+nt][3] + b1);
            }
    }
}

// ---------------------------------------------------------------------------
extern "C" void kernel_launch(void* const* d_in, const int* in_sizes, int n_in,
                              void* d_out, int out_size)
{
    const float* hs   = (const float*)d_in[0];
    const float* mask = (const float*)d_in[1];
    const float* lsc  = (const float*)d_in[2];
    const float* fc1w = (const float*)d_in[3];
    const float* fc1b = (const float*)d_in[4];
    const float* fc2w = (const float*)d_in[5];
    const float* qw   = (const float*)d_in[6];
    const float* qb   = (const float*)d_in[7];
    const float* kw   = (const float*)d_in[8];
    const float* vw   = (const float*)d_in[9];
    const float* vb   = (const float*)d_in[10];
    const float* pw   = (const float*)d_in[11];
    const float* pb   = (const float*)d_in[12];
    float* out = (float*)d_out;

    prep_w_kernel<<<576, 256>>>(qw, kw, vw, pw);
    bias_kernel<<<1, 256>>>(fc1w, fc1b, fc2w);

    cudaFuncSetAttribute(win_attn_hmma, cudaFuncAttributeMaxDynamicSharedMemorySize, SMEM_BYTES);
    win_attn_hmma<<<NWIN, 256, SMEM_BYTES>>>(hs, mask, lsc, qb, vb, pb, out);
}

// round 9
// speedup vs baseline: 1.9872x; 1.9872x over previous
#include <cuda_runtime.h>
#include <cuda_fp16.h>
#include <stdint.h>
#include <math.h>

// ---------------------------------------------------------------------------
// SwinV2 WindowAttention via HMMA, register-resident softmax.
// 4096 windows, N=64 tok, C=192, H=6, HD=32. 2 windows/CTA (M=128), 256 thr.
// ---------------------------------------------------------------------------

#define NBLK 2048
#define STR  200     // halves; 400B row stride (X/Q/K/O), conflict-free
#define VSTR 136     // halves; 272B row stride (Vt), conflict-free

// smem byte offsets
#define OFF_XS 0          // X fp16 [128][STR], later O
#define OFF_QH 51200      // Qhat fp16 [128][STR]
#define OFF_KH 102400     // Khat fp16 [128][STR]
#define OFF_VT 153600     // Vt fp16 [192][VSTR]
#define OFF_SC 205824     // 6 floats
#define SMEM_BYTES 205856

// fragment-ordered weight images: [gemm4][warp8][chunk18][lane32][8 halves]
__device__ __align__(16) __half g_wf[4 * 8 * 4608];
__device__ float g_bias[6 * 64 * 64];

// ---------------- helpers ----------------
__device__ __forceinline__ uint32_t smem_u32(const void* p) {
    uint32_t a;
    asm("{ .reg .u64 t; cvta.to.shared.u64 t, %1; cvt.u32.u64 %0, t; }" : "=r"(a) : "l"(p));
    return a;
}
__device__ __forceinline__ void ldsm4(uint32_t addr, uint32_t r[4]) {
    asm volatile("ldmatrix.sync.aligned.m8n8.x4.shared.b16 {%0,%1,%2,%3}, [%4];"
        : "=r"(r[0]), "=r"(r[1]), "=r"(r[2]), "=r"(r[3]) : "r"(addr));
}
__device__ __forceinline__ void ldsm2(uint32_t addr, uint32_t r[2]) {
    asm volatile("ldmatrix.sync.aligned.m8n8.x2.shared.b16 {%0,%1}, [%2];"
        : "=r"(r[0]), "=r"(r[1]) : "r"(addr));
}
__device__ __forceinline__ void mma16816(float c[4], const uint32_t a[4], uint32_t b0, uint32_t b1) {
    asm volatile("mma.sync.aligned.m16n8k16.row.col.f32.f16.f16.f32 "
        "{%0,%1,%2,%3}, {%4,%5,%6,%7}, {%8,%9}, {%0,%1,%2,%3};"
        : "+f"(c[0]), "+f"(c[1]), "+f"(c[2]), "+f"(c[3])
        : "r"(a[0]), "r"(a[1]), "r"(a[2]), "r"(a[3]), "r"(b0), "r"(b1));
}
__device__ __forceinline__ uint32_t pack2(float a, float b) {
    __half2 h = __floats2half2_rn(a, b);
    return *reinterpret_cast<uint32_t*>(&h);
}

// ---------------- prologue kernels ----------------
// Fragment-ordered B image. For gemm widx, warp w, chunk j = nt*6 + kg,
// lane l, half hh: ks = 2*kg + (hh>>2); b = (hh>>1)&1;
// n = w*24 + nt*8 + (l>>2); k = ks*16 + (l&3)*2 + (hh&1) + b*8; val = W[k][n].
__global__ void prep_wf_kernel(const float* __restrict__ qw, const float* __restrict__ kw,
                               const float* __restrict__ vw, const float* __restrict__ pw)
{
    int i = blockIdx.x * 256 + threadIdx.x;          // 576*256 = 147456
    int widx = i / 36864, r = i % 36864;
    int w = r / 4608, r2 = r % 4608;
    int j = r2 / 256, l = (r2 % 256) / 8, hh = r2 % 8;
    int nt = j / 6, kg = j % 6;
    int ks = 2 * kg + (hh >> 2);
    int b = (hh >> 1) & 1;
    int n = w * 24 + nt * 8 + (l >> 2);
    int k = ks * 16 + (l & 3) * 2 + (hh & 1) + b * 8;
    const float* W = (widx == 0) ? qw : (widx == 1) ? kw : (widx == 2) ? vw : pw;
    g_wf[i] = __float2half(W[k * 192 + n]);
}

__global__ void bias_kernel(const float* __restrict__ fc1_w, const float* __restrict__ fc1_b,
                            const float* __restrict__ fc2_w)
{
    __shared__ float tb[225 * 6];
    int tid = threadIdx.x;
    if (tid < 225) {
        int i = tid / 15, j = tid % 15;
        float v0 = (float)(j - 7) * (8.0f / 7.0f);
        float v1 = (float)(i - 7) * (8.0f / 7.0f);
        float s0 = (v0 > 0.f) ? 1.f : ((v0 < 0.f) ? -1.f : 0.f);
        float s1 = (v1 > 0.f) ? 1.f : ((v1 < 0.f) ? -1.f : 0.f);
        v0 = s0 * log2f(fabsf(v0) + 1.0f) * (1.0f / 3.0f);
        v1 = s1 * log2f(fabsf(v1) + 1.0f) * (1.0f / 3.0f);
        float acc[6];
#pragma unroll
        for (int h = 0; h < 6; h++) acc[h] = 0.f;
        for (int u = 0; u < 512; u++) {
            float hv = fmaxf(v0 * fc1_w[u] + v1 * fc1_w[512 + u] + fc1_b[u], 0.f);
#pragma unroll
            for (int h = 0; h < 6; h++) acc[h] += hv * fc2_w[u * 6 + h];
        }
#pragma unroll
        for (int h = 0; h < 6; h++) tb[tid * 6 + h] = acc[h];
    }
    __syncthreads();
    for (int i = tid; i < 6 * 64 * 64; i += blockDim.x) {
        int h = i >> 12, pq = i & 4095, p = pq >> 6, q = pq & 63;
        int idx = ((p >> 3) - (q >> 3) + 7) * 15 + ((p & 7) - (q & 7) + 7);
        g_bias[i] = 16.0f / (1.0f + __expf(-tb[idx * 6 + h]));
    }
}

// ---------------- main kernel ----------------
// M=128, N=192, K=192 GEMM; warp covers N cols [w*24, w*24+24).
// B fragments LDG'd from fragment-ordered image (L2-resident), prefetch 1.
__device__ __forceinline__ void gemm_qkv(uint32_t a_su, const uint4* wb, int lane,
                                         float acc[8][3][4])
{
#pragma unroll
    for (int mt = 0; mt < 8; mt++)
#pragma unroll
        for (int nt = 0; nt < 3; nt++)
            acc[mt][nt][0] = acc[mt][nt][1] = acc[mt][nt][2] = acc[mt][nt][3] = 0.f;

    const uint32_t arow = lane & 15, ak8 = (lane >> 4) * 8;
    uint4 cur[3], nxt[3];
#pragma unroll
    for (int nt = 0; nt < 3; nt++) cur[nt] = wb[nt * 192 + lane];
#pragma unroll
    for (int ksp = 0; ksp < 6; ksp++) {
        if (ksp < 5) {
#pragma unroll
            for (int nt = 0; nt < 3; nt++) nxt[nt] = wb[(nt * 6 + ksp + 1) * 32 + lane];
        }
#pragma unroll
        for (int hf = 0; hf < 2; hf++) {
            int ks = ksp * 2 + hf;
            uint32_t A[8][4];
#pragma unroll
            for (int mt = 0; mt < 8; mt++)
                ldsm4(a_su + ((mt * 16 + arow) * STR + ks * 16 + ak8) * 2, A[mt]);
#pragma unroll
            for (int nt = 0; nt < 3; nt++) {
                uint32_t b0 = hf ? cur[nt].z : cur[nt].x;
                uint32_t b1 = hf ? cur[nt].w : cur[nt].y;
#pragma unroll
                for (int mt = 0; mt < 8; mt++) mma16816(acc[mt][nt], A[mt], b0, b1);
            }
        }
#pragma unroll
        for (int nt = 0; nt < 3; nt++) cur[nt] = nxt[nt];
    }
}

__global__ void __launch_bounds__(256, 1)
win_attn_hmma(const float* __restrict__ x_g, const float* __restrict__ mask_g,
              const float* __restrict__ lsc,
              const float* __restrict__ qb, const float* __restrict__ vb,
              const float* __restrict__ pb, float* __restrict__ out_g)
{
    extern __shared__ char smc[];
    const uint32_t su = smem_u32(smc);
    const int tid = threadIdx.x, warp = tid >> 5, lane = tid & 31;
    const int blk = blockIdx.x;
    const int r = lane >> 2, cc = (lane & 3) * 2;
    float* scs = (float*)(smc + OFF_SC);
    float acc[8][3][4];

    // ---- load X (2 windows) -> fp16 smem ----
    {
        const float4* xg = (const float4*)(x_g + (size_t)blk * 128 * 192);
#pragma unroll
        for (int i = 0; i < 24; i++) {
            int e = tid + i * 256;               // 6144 float4
            int row = e / 48, c4 = e % 48;
            float4 v = xg[e];
            char* p = smc + OFF_XS + (row * STR + c4 * 4) * 2;
            *(uint32_t*)(p)     = pack2(v.x, v.y);
            *(uint32_t*)(p + 4) = pack2(v.z, v.w);
        }
    }
    if (tid < 6) scs[tid] = __expf(fminf(lsc[tid], 4.60517019f));
    __syncthreads();

    const uint4* wfw = (const uint4*)g_wf + warp * 576;   // warp's image slice stride

    // ---- Q = X @ Wq + qb -> QH fp16 ----
    gemm_qkv(su + OFF_XS, wfw, lane, acc);
#pragma unroll
    for (int mt = 0; mt < 8; mt++)
#pragma unroll
        for (int nt = 0; nt < 3; nt++) {
            int n = warp * 24 + nt * 8 + cc, m = mt * 16 + r;
            float b0 = qb[n], b1 = qb[n + 1];
            *(uint32_t*)(smc + OFF_QH + (m * STR + n) * 2)       = pack2(acc[mt][nt][0] + b0, acc[mt][nt][1] + b1);
            *(uint32_t*)(smc + OFF_QH + ((m + 8) * STR + n) * 2) = pack2(acc[mt][nt][2] + b0, acc[mt][nt][3] + b1);
        }

    // ---- K = X @ Wk -> KH fp16 ----
    gemm_qkv(su + OFF_XS, wfw + 4608, lane, acc);
#pragma unroll
    for (int mt = 0; mt < 8; mt++)
#pragma unroll
        for (int nt = 0; nt < 3; nt++) {
            int n = warp * 24 + nt * 8 + cc, m = mt * 16 + r;
            *(uint32_t*)(smc + OFF_KH + (m * STR + n) * 2)       = pack2(acc[mt][nt][0], acc[mt][nt][1]);
            *(uint32_t*)(smc + OFF_KH + ((m + 8) * STR + n) * 2) = pack2(acc[mt][nt][2], acc[mt][nt][3]);
        }

    // ---- V = X @ Wv + vb -> Vt fp16 (transposed [dim][token]) ----
    gemm_qkv(su + OFF_XS, wfw + 2 * 4608, lane, acc);
#pragma unroll
    for (int mt = 0; mt < 8; mt++)
#pragma unroll
        for (int nt = 0; nt < 3; nt++) {
            int n = warp * 24 + nt * 8 + cc, m = mt * 16 + r;
            float b0 = vb[n], b1 = vb[n + 1];
            *(__half*)(smc + OFF_VT + (n * VSTR + m) * 2)           = __float2half(acc[mt][nt][0] + b0);
            *(__half*)(smc + OFF_VT + ((n + 1) * VSTR + m) * 2)     = __float2half(acc[mt][nt][1] + b1);
            *(__half*)(smc + OFF_VT + (n * VSTR + m + 8) * 2)       = __float2half(acc[mt][nt][2] + b0);
            *(__half*)(smc + OFF_VT + ((n + 1) * VSTR + m + 8) * 2) = __float2half(acc[mt][nt][3] + b1);
        }
    __syncthreads();

    // ---- cosine norms: 768 (m,h) slices, 3/thread ----
#pragma unroll
    for (int i = 0; i < 3; i++) {
        int idx = tid + i * 256;
        int m = idx & 127, h = idx >> 7;
        {   // Q: scale = sc[h]/||q||
            __half2* ptr = (__half2*)(smc + OFF_QH + (m * STR + h * 32) * 2);
            float s = 0.f; __half2 vv[16];
#pragma unroll
            for (int j = 0; j < 16; j++) { vv[j] = ptr[j]; float2 f = __half22float2(vv[j]); s += f.x*f.x + f.y*f.y; }
            float scl = scs[h] * rsqrtf(s);
            __half2 hs = __floats2half2_rn(scl, scl);
#pragma unroll
            for (int j = 0; j < 16; j++) ptr[j] = __hmul2(vv[j], hs);
        }
        {   // K: scale = 1/||k||
            __half2* ptr = (__half2*)(smc + OFF_KH + (m * STR + h * 32) * 2);
            float s = 0.f; __half2 vv[16];
#pragma unroll
            for (int j = 0; j < 16; j++) { vv[j] = ptr[j]; float2 f = __half22float2(vv[j]); s += f.x*f.x + f.y*f.y; }
            float scl = rsqrtf(s);
            __half2 hs = __floats2half2_rn(scl, scl);
#pragma unroll
            for (int j = 0; j < 16; j++) ptr[j] = __hmul2(vv[j], hs);
        }
    }
    __syncthreads();

    // ---- attention: warp = (win, 16-row tile); register softmax; no syncs ----
    {
        const int win = warp >> 2, mt = warp & 3;
        const int m0 = win * 64 + mt * 16;    // smem row base
        const int t0 = mt * 16;               // token row within window
        const uint32_t arow = lane & 15, ak8 = (lane >> 4) * 8;
        const uint32_t brow = lane & 7,  bk8 = ((lane >> 3) & 1) * 8;
        const float* mbase = mask_g + (size_t)((blk * 2 + win) & 1023) * 4096;

#pragma unroll 1
        for (int h = 0; h < 6; h++) {
            // bias + mask in fragment coords (issued early, consumed post-mma)
            float bm0[16], bm1[16];
            const float* bp = g_bias + h * 4096;
            int tr = t0 + r;
#pragma unroll
            for (int nt = 0; nt < 8; nt++) {
                int n = nt * 8 + cc;
                float2 b0 = *(const float2*)(bp + tr * 64 + n);
                float2 k0 = *(const float2*)(mbase + tr * 64 + n);
                float2 b1 = *(const float2*)(bp + (tr + 8) * 64 + n);
                float2 k1 = *(const float2*)(mbase + (tr + 8) * 64 + n);
                bm0[2*nt] = b0.x + k0.x; bm0[2*nt+1] = b0.y + k0.y;
                bm1[2*nt] = b1.x + k1.x; bm1[2*nt+1] = b1.y + k1.y;
            }
            // S = Qhat @ Khat^T : 16 rows x 64 cols, K=32
            uint32_t A0[4], A1[4];
            ldsm4(su + OFF_QH + ((m0 + arow) * STR + h * 32 + ak8) * 2, A0);
            ldsm4(su + OFF_QH + ((m0 + arow) * STR + h * 32 + 16 + ak8) * 2, A1);
            float cs[8][4];
#pragma unroll
            for (int nt = 0; nt < 8; nt++) {
                cs[nt][0] = cs[nt][1] = cs[nt][2] = cs[nt][3] = 0.f;
                uint32_t B0[2], B1[2];
                ldsm2(su + OFF_KH + ((win * 64 + nt * 8 + brow) * STR + h * 32 + bk8) * 2, B0);
                ldsm2(su + OFF_KH + ((win * 64 + nt * 8 + brow) * STR + h * 32 + 16 + bk8) * 2, B1);
                mma16816(cs[nt], A0, B0[0], B0[1]);
                mma16816(cs[nt], A1, B1[0], B1[1]);
            }
            // softmax (rows r and r+8, quad reduction)
            float mx0 = -1e30f, mx1 = -1e30f;
#pragma unroll
            for (int nt = 0; nt < 8; nt++) {
                cs[nt][0] += bm0[2*nt]; cs[nt][1] += bm0[2*nt+1];
                cs[nt][2] += bm1[2*nt]; cs[nt][3] += bm1[2*nt+1];
                mx0 = fmaxf(mx0, fmaxf(cs[nt][0], cs[nt][1]));
                mx1 = fmaxf(mx1, fmaxf(cs[nt][2], cs[nt][3]));
            }
            mx0 = fmaxf(mx0, __shfl_xor_sync(0xffffffffu, mx0, 1));
            mx0 = fmaxf(mx0, __shfl_xor_sync(0xffffffffu, mx0, 2));
            mx1 = fmaxf(mx1, __shfl_xor_sync(0xffffffffu, mx1, 1));
            mx1 = fmaxf(mx1, __shfl_xor_sync(0xffffffffu, mx1, 2));
            float s0 = 0.f, s1 = 0.f;
#pragma unroll
            for (int nt = 0; nt < 8; nt++) {
                cs[nt][0] = __expf(cs[nt][0] - mx0); cs[nt][1] = __expf(cs[nt][1] - mx0);
                cs[nt][2] = __expf(cs[nt][2] - mx1); cs[nt][3] = __expf(cs[nt][3] - mx1);
                s0 += cs[nt][0] + cs[nt][1];
                s1 += cs[nt][2] + cs[nt][3];
            }
            s0 += __shfl_xor_sync(0xffffffffu, s0, 1);
            s0 += __shfl_xor_sync(0xffffffffu, s0, 2);
            s1 += __shfl_xor_sync(0xffffffffu, s1, 1);
            s1 += __shfl_xor_sync(0xffffffffu, s1, 2);
            float i0 = 1.0f / s0, i1 = 1.0f / s1;
            // P fragments (S-accum layout == A layout)
            uint32_t P[4][4];
#pragma unroll
            for (int kt = 0; kt < 4; kt++) {
                P[kt][0] = pack2(cs[2*kt][0]   * i0, cs[2*kt][1]   * i0);
                P[kt][1] = pack2(cs[2*kt][2]   * i1, cs[2*kt][3]   * i1);
                P[kt][2] = pack2(cs[2*kt+1][0] * i0, cs[2*kt+1][1] * i0);
                P[kt][3] = pack2(cs[2*kt+1][2] * i1, cs[2*kt+1][3] * i1);
            }
            // O_h = P @ Vt_h : 16 rows x 32 cols, K=64
            float co[4][4];
#pragma unroll
            for (int nt2 = 0; nt2 < 4; nt2++) {
                co[nt2][0] = co[nt2][1] = co[nt2][2] = co[nt2][3] = 0.f;
#pragma unroll
                for (int ks2 = 0; ks2 < 4; ks2++) {
                    uint32_t B[2];
                    ldsm2(su + OFF_VT + ((h * 32 + nt2 * 8 + brow) * VSTR + win * 64 + ks2 * 16 + bk8) * 2, B);
                    mma16816(co[nt2], P[ks2], B[0], B[1]);
                }
            }
            // write O into XS (X dead)
#pragma unroll
            for (int nt2 = 0; nt2 < 4; nt2++) {
                int n = h * 32 + nt2 * 8 + cc;
                *(uint32_t*)(smc + OFF_XS + ((m0 + r) * STR + n) * 2)     = pack2(co[nt2][0], co[nt2][1]);
                *(uint32_t*)(smc + OFF_XS + ((m0 + r + 8) * STR + n) * 2) = pack2(co[nt2][2], co[nt2][3]);
            }
        }
    }
    __syncthreads();

    // ---- proj = O @ Wp + pb -> gmem ----
    gemm_qkv(su + OFF_XS, wfw + 3 * 4608, lane, acc);
    {
        float* og = out_g + (size_t)blk * 128 * 192;
#pragma unroll
        for (int mt = 0; mt < 8; mt++)
#pragma unroll
            for (int nt = 0; nt < 3; nt++) {
                int n = warp * 24 + nt * 8 + cc, m = mt * 16 + r;
                float b0 = pb[n], b1 = pb[n + 1];
                *(float2*)(og + m * 192 + n)       = make_float2(acc[mt][nt][0] + b0, acc[mt][nt][1] + b1);
                *(float2*)(og + (m + 8) * 192 + n) = make_float2(acc[mt][nt][2] + b0, acc[mt][nt][3] + b1);
            }
    }
}

// ---------------------------------------------------------------------------
extern "C" void kernel_launch(void* const* d_in, const int* in_sizes, int n_in,
                              void* d_out, int out_size)
{
    const float* hs   = (const float*)d_in[0];
    const float* mask = (const float*)d_in[1];
    const float* lsc  = (const float*)d_in[2];
    const float* fc1w = (const float*)d_in[3];
    const float* fc1b = (const float*)d_in[4];
    const float* fc2w = (const float*)d_in[5];
    const float* qw   = (const float*)d_in[6];
    const float* qb   = (const float*)d_in[7];
    const float* kw   = (const float*)d_in[8];
    const float* vw   = (const float*)d_in[9];
    const float* vb   = (const float*)d_in[10];
    const float* pw   = (const float*)d_in[11];
    const float* pb   = (const float*)d_in[12];
    float* out = (float*)d_out;

    prep_wf_kernel<<<576, 256>>>(qw, kw, vw, pw);
    bias_kernel<<<1, 256>>>(fc1w, fc1b, fc2w);

    cudaFuncSetAttribute(win_attn_hmma, cudaFuncAttributeMaxDynamicSharedMemorySize, SMEM_BYTES);
    win_attn_hmma<<<NBLK, 256, SMEM_BYTES>>>(hs, mask, lsc, qb, vb, pb, out);
}

// round 10
// speedup vs baseline: 2.0663x; 1.0398x over previous
#include <cuda_runtime.h>
#include <cuda_fp16.h>
#include <stdint.h>
#include <math.h>

// ---------------------------------------------------------------------------
// SwinV2 WindowAttention via HMMA, register-resident softmax.
// 4096 windows, N=64 tok, C=192, H=6, HD=32. 1 window/CTA (M=64), 256 thr,
// 2 CTAs/SM.
// ---------------------------------------------------------------------------

#define NWIN 4096
#define STR  200     // halves; 400B row stride (X/Q/K/O), ldmatrix conflict-free
#define VSTR 72      // halves; 144B row stride (Vt), ldmatrix conflict-free

// smem byte offsets
#define OFF_XS 0          // X fp16 [64][STR], later O
#define OFF_QH 25600      // Qhat fp16 [64][STR]
#define OFF_KH 51200      // Khat fp16 [64][STR]
#define OFF_VT 76800      // Vt fp16 [192][VSTR] (dim-major, token cols)
#define OFF_SC 104448     // 6 floats
#define SMEM_BYTES 104480

// fragment-ordered weight images: [gemm4][warp8][chunk18][lane32][8 halves]
__device__ __align__(16) __half g_wf[4 * 8 * 4608];
__device__ float g_bias[6 * 64 * 64];

// ---------------- helpers ----------------
__device__ __forceinline__ uint32_t smem_u32(const void* p) {
    uint32_t a;
    asm("{ .reg .u64 t; cvta.to.shared.u64 t, %1; cvt.u32.u64 %0, t; }" : "=r"(a) : "l"(p));
    return a;
}
__device__ __forceinline__ void ldsm4(uint32_t addr, uint32_t r[4]) {
    asm volatile("ldmatrix.sync.aligned.m8n8.x4.shared.b16 {%0,%1,%2,%3}, [%4];"
        : "=r"(r[0]), "=r"(r[1]), "=r"(r[2]), "=r"(r[3]) : "r"(addr));
}
__device__ __forceinline__ void ldsm2(uint32_t addr, uint32_t r[2]) {
    asm volatile("ldmatrix.sync.aligned.m8n8.x2.shared.b16 {%0,%1}, [%2];"
        : "=r"(r[0]), "=r"(r[1]) : "r"(addr));
}
__device__ __forceinline__ void mma16816(float c[4], const uint32_t a[4], uint32_t b0, uint32_t b1) {
    asm volatile("mma.sync.aligned.m16n8k16.row.col.f32.f16.f16.f32 "
        "{%0,%1,%2,%3}, {%4,%5,%6,%7}, {%8,%9}, {%0,%1,%2,%3};"
        : "+f"(c[0]), "+f"(c[1]), "+f"(c[2]), "+f"(c[3])
        : "r"(a[0]), "r"(a[1]), "r"(a[2]), "r"(a[3]), "r"(b0), "r"(b1));
}
__device__ __forceinline__ uint32_t pack2(float a, float b) {
    __half2 h = __floats2half2_rn(a, b);
    return *reinterpret_cast<uint32_t*>(&h);
}

// ---------------- prologue kernels ----------------
// Fragment-ordered B image (same as R9; M-independent).
__global__ void prep_wf_kernel(const float* __restrict__ qw, const float* __restrict__ kw,
                               const float* __restrict__ vw, const float* __restrict__ pw)
{
    int i = blockIdx.x * 256 + threadIdx.x;          // 576*256 = 147456
    int widx = i / 36864, r = i % 36864;
    int w = r / 4608, r2 = r % 4608;
    int j = r2 / 256, l = (r2 % 256) / 8, hh = r2 % 8;
    int nt = j / 6, kg = j % 6;
    int ks = 2 * kg + (hh >> 2);
    int b = (hh >> 1) & 1;
    int n = w * 24 + nt * 8 + (l >> 2);
    int k = ks * 16 + (l & 3) * 2 + (hh & 1) + b * 8;
    const float* W = (widx == 0) ? qw : (widx == 1) ? kw : (widx == 2) ? vw : pw;
    g_wf[i] = __float2half(W[k * 192 + n]);
}

__global__ void bias_kernel(const float* __restrict__ fc1_w, const float* __restrict__ fc1_b,
                            const float* __restrict__ fc2_w)
{
    __shared__ float tb[225 * 6];
    int tid = threadIdx.x;
    if (tid < 225) {
        int i = tid / 15, j = tid % 15;
        float v0 = (float)(j - 7) * (8.0f / 7.0f);
        float v1 = (float)(i - 7) * (8.0f / 7.0f);
        float s0 = (v0 > 0.f) ? 1.f : ((v0 < 0.f) ? -1.f : 0.f);
        float s1 = (v1 > 0.f) ? 1.f : ((v1 < 0.f) ? -1.f : 0.f);
        v0 = s0 * log2f(fabsf(v0) + 1.0f) * (1.0f / 3.0f);
        v1 = s1 * log2f(fabsf(v1) + 1.0f) * (1.0f / 3.0f);
        float acc[6];
#pragma unroll
        for (int h = 0; h < 6; h++) acc[h] = 0.f;
        for (int u = 0; u < 512; u++) {
            float hv = fmaxf(v0 * fc1_w[u] + v1 * fc1_w[512 + u] + fc1_b[u], 0.f);
#pragma unroll
            for (int h = 0; h < 6; h++) acc[h] += hv * fc2_w[u * 6 + h];
        }
#pragma unroll
        for (int h = 0; h < 6; h++) tb[tid * 6 + h] = acc[h];
    }
    __syncthreads();
    for (int i = tid; i < 6 * 64 * 64; i += blockDim.x) {
        int h = i >> 12, pq = i & 4095, p = pq >> 6, q = pq & 63;
        int idx = ((p >> 3) - (q >> 3) + 7) * 15 + ((p & 7) - (q & 7) + 7);
        g_bias[i] = 16.0f / (1.0f + __expf(-tb[idx * 6 + h]));
    }
}

// ---------------- main kernel ----------------
// M=64, N=192, K=192 GEMM; warp covers N cols [w*24, w*24+24).
// B fragments LDG'd from fragment-ordered image (L2-resident), prefetch 1.
__device__ __forceinline__ void gemm_qkv(uint32_t a_su, const uint4* wb, int lane,
                                         float acc[4][3][4])
{
#pragma unroll
    for (int mt = 0; mt < 4; mt++)
#pragma unroll
        for (int nt = 0; nt < 3; nt++)
            acc[mt][nt][0] = acc[mt][nt][1] = acc[mt][nt][2] = acc[mt][nt][3] = 0.f;

    const uint32_t arow = lane & 15, ak8 = (lane >> 4) * 8;
    uint4 cur[3], nxt[3];
#pragma unroll
    for (int nt = 0; nt < 3; nt++) cur[nt] = wb[nt * 192 + lane];
#pragma unroll
    for (int ksp = 0; ksp < 6; ksp++) {
        if (ksp < 5) {
#pragma unroll
            for (int nt = 0; nt < 3; nt++) nxt[nt] = wb[(nt * 6 + ksp + 1) * 32 + lane];
        }
#pragma unroll
        for (int hf = 0; hf < 2; hf++) {
            int ks = ksp * 2 + hf;
            uint32_t A[4][4];
#pragma unroll
            for (int mt = 0; mt < 4; mt++)
                ldsm4(a_su + ((mt * 16 + arow) * STR + ks * 16 + ak8) * 2, A[mt]);
#pragma unroll
            for (int nt = 0; nt < 3; nt++) {
                uint32_t b0 = hf ? cur[nt].z : cur[nt].x;
                uint32_t b1 = hf ? cur[nt].w : cur[nt].y;
#pragma unroll
                for (int mt = 0; mt < 4; mt++) mma16816(acc[mt][nt], A[mt], b0, b1);
            }
        }
#pragma unroll
        for (int nt = 0; nt < 3; nt++) cur[nt] = nxt[nt];
    }
}

__global__ void __launch_bounds__(256, 2)
win_attn_hmma(const float* __restrict__ x_g, const float* __restrict__ mask_g,
              const float* __restrict__ lsc,
              const float* __restrict__ qb, const float* __restrict__ vb,
              const float* __restrict__ pb, float* __restrict__ out_g)
{
    extern __shared__ char smc[];
    const uint32_t su = smem_u32(smc);
    const int tid = threadIdx.x, warp = tid >> 5, lane = tid & 31;
    const int blk = blockIdx.x;
    const int r = lane >> 2, cc = (lane & 3) * 2;
    float* scs = (float*)(smc + OFF_SC);
    float acc[4][3][4];

    // ---- load X -> fp16 smem ----
    {
        const float4* xg = (const float4*)(x_g + (size_t)blk * 64 * 192);
#pragma unroll
        for (int i = 0; i < 12; i++) {
            int e = tid + i * 256;               // 3072 float4
            int row = e / 48, c4 = e % 48;
            float4 v = xg[e];
            char* p = smc + OFF_XS + (row * STR + c4 * 4) * 2;
            *(uint32_t*)(p)     = pack2(v.x, v.y);
            *(uint32_t*)(p + 4) = pack2(v.z, v.w);
        }
    }
    if (tid < 6) scs[tid] = __expf(fminf(lsc[tid], 4.60517019f));
    __syncthreads();

    const uint4* wfw = (const uint4*)g_wf + warp * 576;

    // ---- Q = X @ Wq + qb -> QH fp16 ----
    gemm_qkv(su + OFF_XS, wfw, lane, acc);
#pragma unroll
    for (int mt = 0; mt < 4; mt++)
#pragma unroll
        for (int nt = 0; nt < 3; nt++) {
            int n = warp * 24 + nt * 8 + cc, m = mt * 16 + r;
            float b0 = qb[n], b1 = qb[n + 1];
            *(uint32_t*)(smc + OFF_QH + (m * STR + n) * 2)       = pack2(acc[mt][nt][0] + b0, acc[mt][nt][1] + b1);
            *(uint32_t*)(smc + OFF_QH + ((m + 8) * STR + n) * 2) = pack2(acc[mt][nt][2] + b0, acc[mt][nt][3] + b1);
        }

    // ---- K = X @ Wk -> KH fp16 ----
    gemm_qkv(su + OFF_XS, wfw + 4608, lane, acc);
#pragma unroll
    for (int mt = 0; mt < 4; mt++)
#pragma unroll
        for (int nt = 0; nt < 3; nt++) {
            int n = warp * 24 + nt * 8 + cc, m = mt * 16 + r;
            *(uint32_t*)(smc + OFF_KH + (m * STR + n) * 2)       = pack2(acc[mt][nt][0], acc[mt][nt][1]);
            *(uint32_t*)(smc + OFF_KH + ((m + 8) * STR + n) * 2) = pack2(acc[mt][nt][2], acc[mt][nt][3]);
        }

    // ---- V = X @ Wv + vb -> Vt fp16 (transposed [dim][token]) ----
    gemm_qkv(su + OFF_XS, wfw + 2 * 4608, lane, acc);
#pragma unroll
    for (int mt = 0; mt < 4; mt++)
#pragma unroll
        for (int nt = 0; nt < 3; nt++) {
            int n = warp * 24 + nt * 8 + cc, m = mt * 16 + r;
            float b0 = vb[n], b1 = vb[n + 1];
            *(__half*)(smc + OFF_VT + (n * VSTR + m) * 2)           = __float2half(acc[mt][nt][0] + b0);
            *(__half*)(smc + OFF_VT + ((n + 1) * VSTR + m) * 2)     = __float2half(acc[mt][nt][1] + b1);
            *(__half*)(smc + OFF_VT + (n * VSTR + m + 8) * 2)       = __float2half(acc[mt][nt][2] + b0);
            *(__half*)(smc + OFF_VT + ((n + 1) * VSTR + m + 8) * 2) = __float2half(acc[mt][nt][3] + b1);
        }
    __syncthreads();

    // ---- cosine norms: 384 (m,h) slices ----
    for (int p = tid; p < 384; p += 256) {
        int m = p & 63, h = p >> 6;
        {   // Q: scale = sc[h]/||q||
            __half2* ptr = (__half2*)(smc + OFF_QH + (m * STR + h * 32) * 2);
            float s = 0.f; __half2 vv[16];
#pragma unroll
            for (int j = 0; j < 16; j++) { vv[j] = ptr[j]; float2 f = __half22float2(vv[j]); s += f.x*f.x + f.y*f.y; }
            float scl = scs[h] * rsqrtf(s);
            __half2 hs = __floats2half2_rn(scl, scl);
#pragma unroll
            for (int j = 0; j < 16; j++) ptr[j] = __hmul2(vv[j], hs);
        }
        {   // K: scale = 1/||k||
            __half2* ptr = (__half2*)(smc + OFF_KH + (m * STR + h * 32) * 2);
            float s = 0.f; __half2 vv[16];
#pragma unroll
            for (int j = 0; j < 16; j++) { vv[j] = ptr[j]; float2 f = __half22float2(vv[j]); s += f.x*f.x + f.y*f.y; }
            float scl = rsqrtf(s);
            __half2 hs = __floats2half2_rn(scl, scl);
#pragma unroll
            for (int j = 0; j < 16; j++) ptr[j] = __hmul2(vv[j], hs);
        }
    }
    __syncthreads();

    // ---- attention: warp = (head-group, 16-row tile); register softmax ----
    {
        const int mt = warp & 3, hg = warp >> 2;
        const int m0 = mt * 16;
        const uint32_t arow = lane & 15, ak8 = (lane >> 4) * 8;
        const uint32_t brow = lane & 7,  bk8 = ((lane >> 3) & 1) * 8;
        const float* mbase = mask_g + (size_t)(blk & 1023) * 4096;
        const int tr = m0 + r;

#pragma unroll 1
        for (int hh = 0; hh < 3; hh++) {
            const int h = hg * 3 + hh;
            const float* bp = g_bias + h * 4096;
            // S = Qhat @ Khat^T : 16 rows x 64 cols, K=32
            uint32_t A0[4], A1[4];
            ldsm4(su + OFF_QH + ((m0 + arow) * STR + h * 32 + ak8) * 2, A0);
            ldsm4(su + OFF_QH + ((m0 + arow) * STR + h * 32 + 16 + ak8) * 2, A1);
            float cs[8][4];
#pragma unroll
            for (int nt = 0; nt < 8; nt++) {
                cs[nt][0] = cs[nt][1] = cs[nt][2] = cs[nt][3] = 0.f;
                uint32_t B0[2], B1[2];
                ldsm2(su + OFF_KH + ((nt * 8 + brow) * STR + h * 32 + bk8) * 2, B0);
                ldsm2(su + OFF_KH + ((nt * 8 + brow) * STR + h * 32 + 16 + bk8) * 2, B1);
                mma16816(cs[nt], A0, B0[0], B0[1]);
                mma16816(cs[nt], A1, B1[0], B1[1]);
            }
            // + bias + mask in fragment coords
#pragma unroll
            for (int nt = 0; nt < 8; nt++) {
                int n = nt * 8 + cc;
                float2 b0 = *(const float2*)(bp + tr * 64 + n);
                float2 k0 = *(const float2*)(mbase + tr * 64 + n);
                float2 b1 = *(const float2*)(bp + (tr + 8) * 64 + n);
                float2 k1 = *(const float2*)(mbase + (tr + 8) * 64 + n);
                cs[nt][0] += b0.x + k0.x; cs[nt][1] += b0.y + k0.y;
                cs[nt][2] += b1.x + k1.x; cs[nt][3] += b1.y + k1.y;
            }
            // softmax (rows r and r+8, quad reduction)
            float mx0 = -1e30f, mx1 = -1e30f;
#pragma unroll
            for (int nt = 0; nt < 8; nt++) {
                mx0 = fmaxf(mx0, fmaxf(cs[nt][0], cs[nt][1]));
                mx1 = fmaxf(mx1, fmaxf(cs[nt][2], cs[nt][3]));
            }
            mx0 = fmaxf(mx0, __shfl_xor_sync(0xffffffffu, mx0, 1));
            mx0 = fmaxf(mx0, __shfl_xor_sync(0xffffffffu, mx0, 2));
            mx1 = fmaxf(mx1, __shfl_xor_sync(0xffffffffu, mx1, 1));
            mx1 = fmaxf(mx1, __shfl_xor_sync(0xffffffffu, mx1, 2));
            float s0 = 0.f, s1 = 0.f;
#pragma unroll
            for (int nt = 0; nt < 8; nt++) {
                cs[nt][0] = __expf(cs[nt][0] - mx0); cs[nt][1] = __expf(cs[nt][1] - mx0);
                cs[nt][2] = __expf(cs[nt][2] - mx1); cs[nt][3] = __expf(cs[nt][3] - mx1);
                s0 += cs[nt][0] + cs[nt][1];
                s1 += cs[nt][2] + cs[nt][3];
            }
            s0 += __shfl_xor_sync(0xffffffffu, s0, 1);
            s0 += __shfl_xor_sync(0xffffffffu, s0, 2);
            s1 += __shfl_xor_sync(0xffffffffu, s1, 1);
            s1 += __shfl_xor_sync(0xffffffffu, s1, 2);
            float i0 = 1.0f / s0, i1 = 1.0f / s1;
            // P fragments (S-accum layout == A layout)
            uint32_t P[4][4];
#pragma unroll
            for (int kt = 0; kt < 4; kt++) {
                P[kt][0] = pack2(cs[2*kt][0]   * i0, cs[2*kt][1]   * i0);
                P[kt][1] = pack2(cs[2*kt][2]   * i1, cs[2*kt][3]   * i1);
                P[kt][2] = pack2(cs[2*kt+1][0] * i0, cs[2*kt+1][1] * i0);
                P[kt][3] = pack2(cs[2*kt+1][2] * i1, cs[2*kt+1][3] * i1);
            }
            // O_h = P @ Vt_h : 16 rows x 32 cols, K=64
            float co[4][4];
#pragma unroll
            for (int nt2 = 0; nt2 < 4; nt2++) {
                co[nt2][0] = co[nt2][1] = co[nt2][2] = co[nt2][3] = 0.f;
#pragma unroll
                for (int ks2 = 0; ks2 < 4; ks2++) {
                    uint32_t B[2];
                    ldsm2(su + OFF_VT + ((h * 32 + nt2 * 8 + brow) * VSTR + ks2 * 16 + bk8) * 2, B);
                    mma16816(co[nt2], P[ks2], B[0], B[1]);
                }
            }
            // write O into XS (X dead)
#pragma unroll
            for (int nt2 = 0; nt2 < 4; nt2++) {
                int n = h * 32 + nt2 * 8 + cc;
                *(uint32_t*)(smc + OFF_XS + ((m0 + r) * STR + n) * 2)     = pack2(co[nt2][0], co[nt2][1]);
                *(uint32_t*)(smc + OFF_XS + ((m0 + r + 8) * STR + n) * 2) = pack2(co[nt2][2], co[nt2][3]);
            }
        }
    }
    __syncthreads();

    // ---- proj = O @ Wp + pb -> gmem ----
    gemm_qkv(su + OFF_XS, wfw + 3 * 4608, lane, acc);
    {
        float* og = out_g + (size_t)blk * 64 * 192;
#pragma unroll
        for (int mt = 0; mt < 4; mt++)
#pragma unroll
            for (int nt = 0; nt < 3; nt++) {
                int n = warp * 24 + nt * 8 + cc, m = mt * 16 + r;
                float b0 = pb[n], b1 = pb[n + 1];
                *(float2*)(og + m * 192 + n)       = make_float2(acc[mt][nt][0] + b0, acc[mt][nt][1] + b1);
                *(float2*)(og + (m + 8) * 192 + n) = make_float2(acc[mt][nt][2] + b0, acc[mt][nt][3] + b1);
            }
    }
}

// ---------------------------------------------------------------------------
extern "C" void kernel_launch(void* const* d_in, const int* in_sizes, int n_in,
                              void* d_out, int out_size)
{
    const float* hs   = (const float*)d_in[0];
    const float* mask = (const float*)d_in[1];
    const float* lsc  = (const float*)d_in[2];
    const float* fc1w = (const float*)d_in[3];
    const float* fc1b = (const float*)d_in[4];
    const float* fc2w = (const float*)d_in[5];
    const float* qw   = (const float*)d_in[6];
    const float* qb   = (const float*)d_in[7];
    const float* kw   = (const float*)d_in[8];
    const float* vw   = (const float*)d_in[9];
    const float* vb   = (const float*)d_in[10];
    const float* pw   = (const float*)d_in[11];
    const float* pb   = (const float*)d_in[12];
    float* out = (float*)d_out;

    prep_wf_kernel<<<576, 256>>>(qw, kw, vw, pw);
    bias_kernel<<<1, 256>>>(fc1w, fc1b, fc2w);

    cudaFuncSetAttribute(win_attn_hmma, cudaFuncAttributeMaxDynamicSharedMemorySize, SMEM_BYTES);
    win_attn_hmma<<<NWIN, 256, SMEM_BYTES>>>(hs, mask, lsc, qb, vb, pb, out);
}

// round 12
// speedup vs baseline: 2.1734x; 1.0519x over previous
#include <cuda_runtime.h>
#include <cuda_fp16.h>
#include <stdint.h>
#include <math.h>

// ---------------------------------------------------------------------------
// SwinV2 WindowAttention via HMMA, register-resident softmax.
// 4096 windows, N=64 tok, C=192, H=6, HD=32. 1 window/CTA (M=64), 256 thr,
// 2 CTAs/SM.
// ---------------------------------------------------------------------------

#define NWIN 4096
#define STR  200     // halves; 400B row stride (X/Q/K/O), ldmatrix conflict-free
#define VSTR 72      // halves; 144B row stride (Vt), ldmatrix conflict-free

// smem byte offsets
#define OFF_XS 0          // X fp16 [64][STR], later O
#define OFF_QH 25600      // Qhat fp16 [64][STR]
#define OFF_KH 51200      // Khat fp16 [64][STR]
#define OFF_VT 76800      // Vt fp16 [192][VSTR] (dim-major, token cols)
#define OFF_SC 104448     // 6 floats
#define SMEM_BYTES 104480

// fragment-ordered weight images: [gemm4][warp8][chunk18][lane32][8 halves]
__device__ __align__(16) __half g_wf[4 * 8 * 4608];
__device__ float g_bias[6 * 64 * 64];

// ---------------- helpers ----------------
__device__ __forceinline__ uint32_t smem_u32(const void* p) {
    uint32_t a;
    asm("{ .reg .u64 t; cvta.to.shared.u64 t, %1; cvt.u32.u64 %0, t; }" : "=r"(a) : "l"(p));
    return a;
}
__device__ __forceinline__ void ldsm4(uint32_t addr, uint32_t r[4]) {
    asm volatile("ldmatrix.sync.aligned.m8n8.x4.shared.b16 {%0,%1,%2,%3}, [%4];"
        : "=r"(r[0]), "=r"(r[1]), "=r"(r[2]), "=r"(r[3]) : "r"(addr));
}
__device__ __forceinline__ void ldsm2(uint32_t addr, uint32_t r[2]) {
    asm volatile("ldmatrix.sync.aligned.m8n8.x2.shared.b16 {%0,%1}, [%2];"
        : "=r"(r[0]), "=r"(r[1]) : "r"(addr));
}
__device__ __forceinline__ void mma16816(float c[4], const uint32_t a[4], uint32_t b0, uint32_t b1) {
    asm volatile("mma.sync.aligned.m16n8k16.row.col.f32.f16.f16.f32 "
        "{%0,%1,%2,%3}, {%4,%5,%6,%7}, {%8,%9}, {%0,%1,%2,%3};"
        : "+f"(c[0]), "+f"(c[1]), "+f"(c[2]), "+f"(c[3])
        : "r"(a[0]), "r"(a[1]), "r"(a[2]), "r"(a[3]), "r"(b0), "r"(b1));
}
__device__ __forceinline__ uint32_t pack2(float a, float b) {
    __half2 h = __floats2half2_rn(a, b);
    return *reinterpret_cast<uint32_t*>(&h);
}

// ---------------- merged prologue kernel ----------------
// Blocks 0..575: fragment-ordered fp16 weight images.
// Block 576: continuous position bias MLP -> g_bias.
__global__ void prep_all_kernel(const float* __restrict__ qw, const float* __restrict__ kw,
                                const float* __restrict__ vw, const float* __restrict__ pw,
                                const float* __restrict__ fc1_w, const float* __restrict__ fc1_b,
                                const float* __restrict__ fc2_w)
{
    if (blockIdx.x < 576) {
        int i = blockIdx.x * 256 + threadIdx.x;          // 576*256 = 147456
        int widx = i / 36864, r = i % 36864;
        int w = r / 4608, r2 = r % 4608;
        int j = r2 / 256, l = (r2 % 256) / 8, hh = r2 % 8;
        int nt = j / 6, kg = j % 6;
        int ks = 2 * kg + (hh >> 2);
        int b = (hh >> 1) & 1;
        int n = w * 24 + nt * 8 + (l >> 2);
        int k = ks * 16 + (l & 3) * 2 + (hh & 1) + b * 8;
        const float* W = (widx == 0) ? qw : (widx == 1) ? kw : (widx == 2) ? vw : pw;
        g_wf[i] = __float2half(W[k * 192 + n]);
        return;
    }
    // ---- bias block ----
    __shared__ float tb[225 * 6];
    int tid = threadIdx.x;
    if (tid < 225) {
        int i = tid / 15, j = tid % 15;
        float v0 = (float)(j - 7) * (8.0f / 7.0f);
        float v1 = (float)(i - 7) * (8.0f / 7.0f);
        float s0 = (v0 > 0.f) ? 1.f : ((v0 < 0.f) ? -1.f : 0.f);
        float s1 = (v1 > 0.f) ? 1.f : ((v1 < 0.f) ? -1.f : 0.f);
        v0 = s0 * log2f(fabsf(v0) + 1.0f) * (1.0f / 3.0f);
        v1 = s1 * log2f(fabsf(v1) + 1.0f) * (1.0f / 3.0f);
        float acc[6];
#pragma unroll
        for (int h = 0; h < 6; h++) acc[h] = 0.f;
        for (int u = 0; u < 512; u++) {
            float hv = fmaxf(v0 * fc1_w[u] + v1 * fc1_w[512 + u] + fc1_b[u], 0.f);
#pragma unroll
            for (int h = 0; h < 6; h++) acc[h] += hv * fc2_w[u * 6 + h];
        }
#pragma unroll
        for (int h = 0; h < 6; h++) tb[tid * 6 + h] = acc[h];
    }
    __syncthreads();
    for (int i = tid; i < 6 * 64 * 64; i += blockDim.x) {
        int h = i >> 12, pq = i & 4095, p = pq >> 6, q = pq & 63;
        int idx = ((p >> 3) - (q >> 3) + 7) * 15 + ((p & 7) - (q & 7) + 7);
        g_bias[i] = 16.0f / (1.0f + __expf(-tb[idx * 6 + h]));
    }
}

// ---------------- main kernel ----------------
// M=64, N=192, K=192 GEMM; warp covers N cols [w*24, w*24+24).
// B fragments LDG'd from fragment-ordered image (L2-resident), prefetch 1.
__device__ __forceinline__ void gemm_qkv(uint32_t a_su, const uint4* wb, int lane,
                                         float acc[4][3][4])
{
#pragma unroll
    for (int mt = 0; mt < 4; mt++)
#pragma unroll
        for (int nt = 0; nt < 3; nt++)
            acc[mt][nt][0] = acc[mt][nt][1] = acc[mt][nt][2] = acc[mt][nt][3] = 0.f;

    const uint32_t arow = lane & 15, ak8 = (lane >> 4) * 8;
    uint4 cur[3], nxt[3];
#pragma unroll
    for (int nt = 0; nt < 3; nt++) cur[nt] = wb[nt * 192 + lane];
#pragma unroll
    for (int ksp = 0; ksp < 6; ksp++) {
        if (ksp < 5) {
#pragma unroll
            for (int nt = 0; nt < 3; nt++) nxt[nt] = wb[(nt * 6 + ksp + 1) * 32 + lane];
        }
#pragma unroll
        for (int hf = 0; hf < 2; hf++) {
            int ks = ksp * 2 + hf;
            uint32_t A[4][4];
#pragma unroll
            for (int mt = 0; mt < 4; mt++)
                ldsm4(a_su + ((mt * 16 + arow) * STR + ks * 16 + ak8) * 2, A[mt]);
#pragma unroll
            for (int nt = 0; nt < 3; nt++) {
                uint32_t b0 = hf ? cur[nt].z : cur[nt].x;
                uint32_t b1 = hf ? cur[nt].w : cur[nt].y;
#pragma unroll
                for (int mt = 0; mt < 4; mt++) mma16816(acc[mt][nt], A[mt], b0, b1);
            }
        }
#pragma unroll
        for (int nt = 0; nt < 3; nt++) cur[nt] = nxt[nt];
    }
}

__global__ void __launch_bounds__(256, 2)
win_attn_hmma(const float* __restrict__ x_g, const float* __restrict__ mask_g,
              const float* __restrict__ lsc,
              const float* __restrict__ qb, const float* __restrict__ vb,
              const float* __restrict__ pb, float* __restrict__ out_g)
{
    extern __shared__ char smc[];
    const uint32_t su = smem_u32(smc);
    const int tid = threadIdx.x, warp = tid >> 5, lane = tid & 31;
    const int blk = blockIdx.x;
    const int r = lane >> 2, cc = (lane & 3) * 2;
    float* scs = (float*)(smc + OFF_SC);
    float acc[4][3][4];

    // ---- load X -> fp16 smem ----
    {
        const float4* xg = (const float4*)(x_g + (size_t)blk * 64 * 192);
#pragma unroll
        for (int i = 0; i < 12; i++) {
            int e = tid + i * 256;               // 3072 float4
            int row = e / 48, c4 = e % 48;
            float4 v = xg[e];
            char* p = smc + OFF_XS + (row * STR + c4 * 4) * 2;
            *(uint32_t*)(p)     = pack2(v.x, v.y);
            *(uint32_t*)(p + 4) = pack2(v.z, v.w);
        }
    }
    if (tid < 6) scs[tid] = __expf(fminf(lsc[tid], 4.60517019f));
    __syncthreads();

    const uint4* wfw = (const uint4*)g_wf + warp * 576;

    // ---- Q = X @ Wq + qb -> QH fp16 ----
    gemm_qkv(su + OFF_XS, wfw, lane, acc);
#pragma unroll
    for (int mt = 0; mt < 4; mt++)
#pragma unroll
        for (int nt = 0; nt < 3; nt++) {
            int n = warp * 24 + nt * 8 + cc, m = mt * 16 + r;
            float b0 = qb[n], b1 = qb[n + 1];
            *(uint32_t*)(smc + OFF_QH + (m * STR + n) * 2)       = pack2(acc[mt][nt][0] + b0, acc[mt][nt][1] + b1);
            *(uint32_t*)(smc + OFF_QH + ((m + 8) * STR + n) * 2) = pack2(acc[mt][nt][2] + b0, acc[mt][nt][3] + b1);
        }

    // ---- K = X @ Wk -> KH fp16 ----
    gemm_qkv(su + OFF_XS, wfw + 4608, lane, acc);
#pragma unroll
    for (int mt = 0; mt < 4; mt++)
#pragma unroll
        for (int nt = 0; nt < 3; nt++) {
            int n = warp * 24 + nt * 8 + cc, m = mt * 16 + r;
            *(uint32_t*)(smc + OFF_KH + (m * STR + n) * 2)       = pack2(acc[mt][nt][0], acc[mt][nt][1]);
            *(uint32_t*)(smc + OFF_KH + ((m + 8) * STR + n) * 2) = pack2(acc[mt][nt][2], acc[mt][nt][3]);
        }

    // ---- V = X @ Wv + vb -> Vt fp16 (transposed [dim][token]) ----
    gemm_qkv(su + OFF_XS, wfw + 2 * 4608, lane, acc);
#pragma unroll
    for (int mt = 0; mt < 4; mt++)
#pragma unroll
        for (int nt = 0; nt < 3; nt++) {
            int n = warp * 24 + nt * 8 + cc, m = mt * 16 + r;
            float b0 = vb[n], b1 = vb[n + 1];
            *(__half*)(smc + OFF_VT + (n * VSTR + m) * 2)           = __float2half(acc[mt][nt][0] + b0);
            *(__half*)(smc + OFF_VT + ((n + 1) * VSTR + m) * 2)     = __float2half(acc[mt][nt][1] + b1);
            *(__half*)(smc + OFF_VT + (n * VSTR + m + 8) * 2)       = __float2half(acc[mt][nt][2] + b0);
            *(__half*)(smc + OFF_VT + ((n + 1) * VSTR + m + 8) * 2) = __float2half(acc[mt][nt][3] + b1);
        }
    __syncthreads();

    // ---- cosine norms: 384 (m,h) slices ----
    for (int p = tid; p < 384; p += 256) {
        int m = p & 63, h = p >> 6;
        {   // Q: scale = sc[h]/||q||
            __half2* ptr = (__half2*)(smc + OFF_QH + (m * STR + h * 32) * 2);
            float s = 0.f; __half2 vv[16];
#pragma unroll
            for (int j = 0; j < 16; j++) { vv[j] = ptr[j]; float2 f = __half22float2(vv[j]); s += f.x*f.x + f.y*f.y; }
            float scl = scs[h] * rsqrtf(s);
            __half2 hs = __floats2half2_rn(scl, scl);
#pragma unroll
            for (int j = 0; j < 16; j++) ptr[j] = __hmul2(vv[j], hs);
        }
        {   // K: scale = 1/||k||
            __half2* ptr = (__half2*)(smc + OFF_KH + (m * STR + h * 32) * 2);
            float s = 0.f; __half2 vv[16];
#pragma unroll
            for (int j = 0; j < 16; j++) { vv[j] = ptr[j]; float2 f = __half22float2(vv[j]); s += f.x*f.x + f.y*f.y; }
            float scl = rsqrtf(s);
            __half2 hs = __floats2half2_rn(scl, scl);
#pragma unroll
            for (int j = 0; j < 16; j++) ptr[j] = __hmul2(vv[j], hs);
        }
    }
    __syncthreads();

    // ---- attention: warp = (head-group, 16-row tile); register softmax ----
    {
        const int mt = warp & 3, hg = warp >> 2;
        const int m0 = mt * 16;
        const uint32_t arow = lane & 15, ak8 = (lane >> 4) * 8;
        const uint32_t brow = lane & 7,  bk8 = ((lane >> 3) & 1) * 8;
        const float* mbase = mask_g + (size_t)(blk & 1023) * 4096;
        const int tr = m0 + r;

        // mask fragments are head-independent: load ONCE for the 3 heads
        float km0[16], km1[16];
#pragma unroll
        for (int nt = 0; nt < 8; nt++) {
            int n = nt * 8 + cc;
            float2 k0 = *(const float2*)(mbase + tr * 64 + n);
            float2 k1 = *(const float2*)(mbase + (tr + 8) * 64 + n);
            km0[2*nt] = k0.x; km0[2*nt+1] = k0.y;
            km1[2*nt] = k1.x; km1[2*nt+1] = k1.y;
        }

#pragma unroll 1
        for (int hh = 0; hh < 3; hh++) {
            const int h = hg * 3 + hh;
            const float* bp = g_bias + h * 4096;
            // S = Qhat @ Khat^T : 16 rows x 64 cols, K=32
            uint32_t A0[4], A1[4];
            ldsm4(su + OFF_QH + ((m0 + arow) * STR + h * 32 + ak8) * 2, A0);
            ldsm4(su + OFF_QH + ((m0 + arow) * STR + h * 32 + 16 + ak8) * 2, A1);
            float cs[8][4];
#pragma unroll
            for (int nt = 0; nt < 8; nt++) {
                cs[nt][0] = cs[nt][1] = cs[nt][2] = cs[nt][3] = 0.f;
                uint32_t B0[2], B1[2];
                ldsm2(su + OFF_KH + ((nt * 8 + brow) * STR + h * 32 + bk8) * 2, B0);
                ldsm2(su + OFF_KH + ((nt * 8 + brow) * STR + h * 32 + 16 + bk8) * 2, B1);
                mma16816(cs[nt], A0, B0[0], B0[1]);
                mma16816(cs[nt], A1, B1[0], B1[1]);
            }
            // + bias (per head) + mask (hoisted) in fragment coords
#pragma unroll
            for (int nt = 0; nt < 8; nt++) {
                int n = nt * 8 + cc;
                float2 b0 = *(const float2*)(bp + tr * 64 + n);
                float2 b1 = *(const float2*)(bp + (tr + 8) * 64 + n);
                cs[nt][0] += b0.x + km0[2*nt]; cs[nt][1] += b0.y + km0[2*nt+1];
                cs[nt][2] += b1.x + km1[2*nt]; cs[nt][3] += b1.y + km1[2*nt+1];
            }
            // softmax (rows r and r+8, quad reduction)
            float mx0 = -1e30f, mx1 = -1e30f;
#pragma unroll
            for (int nt = 0; nt < 8; nt++) {
                mx0 = fmaxf(mx0, fmaxf(cs[nt][0], cs[nt][1]));
                mx1 = fmaxf(mx1, fmaxf(cs[nt][2], cs[nt][3]));
            }
            mx0 = fmaxf(mx0, __shfl_xor_sync(0xffffffffu, mx0, 1));
            mx0 = fmaxf(mx0, __shfl_xor_sync(0xffffffffu, mx0, 2));
            mx1 = fmaxf(mx1, __shfl_xor_sync(0xffffffffu, mx1, 1));
            mx1 = fmaxf(mx1, __shfl_xor_sync(0xffffffffu, mx1, 2));
            float s0 = 0.f, s1 = 0.f;
#pragma unroll
            for (int nt = 0; nt < 8; nt++) {
                cs[nt][0] = __expf(cs[nt][0] - mx0); cs[nt][1] = __expf(cs[nt][1] - mx0);
                cs[nt][2] = __expf(cs[nt][2] - mx1); cs[nt][3] = __expf(cs[nt][3] - mx1);
                s0 += cs[nt][0] + cs[nt][1];
                s1 += cs[nt][2] + cs[nt][3];
            }
            s0 += __shfl_xor_sync(0xffffffffu, s0, 1);
            s0 += __shfl_xor_sync(0xffffffffu, s0, 2);
            s1 += __shfl_xor_sync(0xffffffffu, s1, 1);
            s1 += __shfl_xor_sync(0xffffffffu, s1, 2);
            float i0 = 1.0f / s0, i1 = 1.0f / s1;
            // P fragments (S-accum layout == A layout)
            uint32_t P[4][4];
#pragma unroll
            for (int kt = 0; kt < 4; kt++) {
                P[kt][0] = pack2(cs[2*kt][0]   * i0, cs[2*kt][1]   * i0);
                P[kt][1] = pack2(cs[2*kt][2]   * i1, cs[2*kt][3]   * i1);
                P[kt][2] = pack2(cs[2*kt+1][0] * i0, cs[2*kt+1][1] * i0);
                P[kt][3] = pack2(cs[2*kt+1][2] * i1, cs[2*kt+1][3] * i1);
            }
            // O_h = P @ Vt_h : 16 rows x 32 cols, K=64
            float co[4][4];
#pragma unroll
            for (int nt2 = 0; nt2 < 4; nt2++) {
                co[nt2][0] = co[nt2][1] = co[nt2][2] = co[nt2][3] = 0.f;
#pragma unroll
                for (int ks2 = 0; ks2 < 4; ks2++) {
                    uint32_t B[2];
                    ldsm2(su + OFF_VT + ((h * 32 + nt2 * 8 + brow) * VSTR + ks2 * 16 + bk8) * 2, B);
                    mma16816(co[nt2], P[ks2], B[0], B[1]);
                }
            }
            // write O into XS (X dead)
#pragma unroll
            for (int nt2 = 0; nt2 < 4; nt2++) {
                int n = h * 32 + nt2 * 8 + cc;
                *(uint32_t*)(smc + OFF_XS + ((m0 + r) * STR + n) * 2)     = pack2(co[nt2][0], co[nt2][1]);
                *(uint32_t*)(smc + OFF_XS + ((m0 + r + 8) * STR + n) * 2) = pack2(co[nt2][2], co[nt2][3]);
            }
        }
    }
    __syncthreads();

    // ---- proj = O @ Wp + pb -> gmem ----
    gemm_qkv(su + OFF_XS, wfw + 3 * 4608, lane, acc);
    {
        float* og = out_g + (size_t)blk * 64 * 192;
#pragma unroll
        for (int mt = 0; mt < 4; mt++)
#pragma unroll
            for (int nt = 0; nt < 3; nt++) {
                int n = warp * 24 + nt * 8 + cc, m = mt * 16 + r;
                float b0 = pb[n], b1 = pb[n + 1];
                *(float2*)(og + m * 192 + n)       = make_float2(acc[mt][nt][0] + b0, acc[mt][nt][1] + b1);
                *(float2*)(og + (m + 8) * 192 + n) = make_float2(acc[mt][nt][2] + b0, acc[mt][nt][3] + b1);
            }
    }
}

// ---------------------------------------------------------------------------
extern "C" void kernel_launch(void* const* d_in, const int* in_sizes, int n_in,
                              void* d_out, int out_size)
{
    const float* hs   = (const float*)d_in[0];
    const float* mask = (const float*)d_in[1];
    const float* lsc  = (const float*)d_in[2];
    const float* fc1w = (const float*)d_in[3];
    const float* fc1b = (const float*)d_in[4];
    const float* fc2w = (const float*)d_in[5];
    const float* qw   = (const float*)d_in[6];
    const float* qb   = (const float*)d_in[7];
    const float* kw   = (const float*)d_in[8];
    const float* vw   = (const float*)d_in[9];
    const float* vb   = (const float*)d_in[10];
    const float* pw   = (const float*)d_in[11];
    const float* pb   = (const float*)d_in[12];
    float* out = (float*)d_out;

    prep_all_kernel<<<577, 256>>>(qw, kw, vw, pw, fc1w, fc1b, fc2w);

    cudaFuncSetAttribute(win_attn_hmma, cudaFuncAttributeMaxDynamicSharedMemorySize, SMEM_BYTES);
    win_attn_hmma<<<NWIN, 256, SMEM_BYTES>>>(hs, mask, lsc, qb, vb, pb, out);
}